// round 16
// baseline (speedup 1.0000x reference)
#include <cuda_runtime.h>
#include <math.h>

#define CC 128
#define BB 16384
#define NBLK 1024             // 4096 warps -> exactly 4 rows/warp, one wave
#define NTHR 128
#define WPB 4                 // warps per block
#define TOTW (NBLK*WPB)       // 4096 warps

#define EPSF 1e-5f
#define LN2   0.6931471805599453f
#define LOG2E 1.4426950408889634f
// base-2 clamp bounds: log2(1e-5), log2(1-1e-5)
#define LOG2_EPS   -16.609640474436812f
#define LOG2_1MEPS -1.4427023e-05f

#define CLMP2(v) fminf(fmaxf((v), LOG2_EPS), LOG2_1MEPS)
#define CLIP01(a) fminf(fmaxf((a), EPSF), 1.f - EPSF)
// softplus(d), |d|<1, deg-6 Taylor (max abs err ~2.6e-5) -- natural log domain
#define SPOLY(d, s2) (LN2 + 0.5f*(d) + (s2)*(0.125f + (s2)*(-5.2083333e-3f + (s2)*3.4722222e-4f)))

#define FULLM 0xffffffffu

__device__ __forceinline__ float ex2f(float x){ float y; asm("ex2.approx.ftz.f32 %0,%1;" : "=f"(y) : "f"(x)); return y; }
__device__ __forceinline__ float lg2f(float x){ float y; asm("lg2.approx.ftz.f32 %0,%1;" : "=f"(y) : "f"(x)); return y; }

// ---- scratch (no allocations allowed) ----
__device__ float g_pb[NBLK];
__device__ float g_pr[NBLK];
__device__ int   g_pi[CC];     // parent lane (0..15) per column, or 16 if none
__device__ float g_cf[CC];     // regularizer coef per column (0 if none)
__device__ float g_nnz;
__device__ unsigned int g_done = 0;  // last-block ticket (self-resetting)

// ---------------------------------------------------------------------------
// Prep: one block per column; ballot-based extraction.
// pi = unique nondiag zero row of prior_me column c (the parent, 0..15),
// or 16 (lane holding the no-correction denominator). cf = v/rowsum or 0.
// ---------------------------------------------------------------------------
__global__ void __launch_bounds__(CC)
prep_kernel(const float* __restrict__ prior_me,
            const float* __restrict__ prior_ms)
{
    __shared__ float    s_rs[CC];
    __shared__ unsigned s_bme[4], s_brs[4];
    const int c    = blockIdx.x;
    const int r    = threadIdx.x;
    const int warp = r >> 5;
    const int lane = r & 31;

    const float4* rp = (const float4*)(prior_ms + r * CC);
    float s = 0.f;
    #pragma unroll
    for (int j = 0; j < CC / 4; j++){
        float4 v = rp[j];
        s += v.x + v.y + v.z + v.w;
    }
    s_rs[r] = s;
    float mev = prior_me[r * CC + c];

    bool pme = (mev == 0.f) && (r != c);
    bool prs = (s > 0.f);
    unsigned bme = __ballot_sync(FULLM, pme);
    unsigned brs = __ballot_sync(FULLM, prs);
    if (lane == 0){ s_bme[warp] = bme; s_brs[warp] = brs; }
    __syncthreads();

    if (r == 0){
        int pid = -1;
        #pragma unroll
        for (int w = 0; w < 4; w++){
            unsigned m = s_bme[w];
            if (m && pid < 0) pid = w * 32 + (__ffs(m) - 1);
        }
        float cf = 0.f;
        if (pid >= 0){
            float v = prior_ms[pid * CC + c];
            if (v != 0.f && s_rs[pid] > 0.f) cf = v / s_rs[pid];
        }
        g_pi[c] = (pid >= 0) ? pid : 16;   // 16 = "no parent" lane sentinel
        g_cf[c] = cf;
    }
    if (r == 32 && c == 0){
        g_nnz = (float)(__popc(s_brs[0]) + __popc(s_brs[1]) +
                        __popc(s_brs[2]) + __popc(s_brs[3]));
    }
}

// ---------------------------------------------------------------------------
// Main fused kernel, base-2 log domain, STRIDED lane layout: lane owns
// c = lane + 32k. Parents (cols 0..15) live at k=0 of lanes 0..15, so all
// parent gathers are single SHFL.IDX -- no smem row buffers, no __syncwarp.
// Softmax denominators (17 distinct per row) computed once per lane and
// shuffled (shared lg2/rcp). Finish fused via last-block fp64 reduce.
// ---------------------------------------------------------------------------
__global__ void __launch_bounds__(NTHR, 8)
main_kernel(const float* __restrict__ logits,
            const float* __restrict__ target,
            const float* __restrict__ weight,
            const float* __restrict__ v1s, const float* __restrict__ v2s,
            const float* __restrict__ v1m, const float* __restrict__ v2m,
            float* __restrict__ out)
{
    __shared__ float s_ss[3][CC];       // sigmoid shifts, prescaled by LOG2E
    __shared__ float s_sm[3][CC];       // softmax shifts, prescaled by LOG2E
    __shared__ float s_redb[WPB], s_redr[WPB];
    __shared__ bool  s_last;

    for (int c = threadIdx.x; c < CC; c += NTHR){
        float a1 = v1s[c], a2 = v2s[c];
        s_ss[0][c] = 0.f;
        s_ss[1][c] = a1 * LOG2E;
        s_ss[2][c] = (a1 - a2) * LOG2E;
        float m1 = v1m[c], m2 = v2m[c];
        s_sm[0][c] = 0.f;
        s_sm[1][c] = m1 * LOG2E;
        s_sm[2][c] = (m1 - m2) * LOG2E;
    }
    __syncthreads();

    const int warp = threadIdx.x >> 5;
    const int lane = threadIdx.x & 31;
    const int gw   = blockIdx.x * WPB + warp;

    int   pi[4];
    float cf[4], wv[4];
    #pragma unroll
    for (int k = 0; k < 4; k++){
        int c = lane + 32 * k;
        pi[k] = g_pi[c];
        cf[k] = g_cf[c];
        wv[k] = weight[c];
    }

    float bs0 = 0.f, bs1 = 0.f;   // BCE accumulators (base-2 log units)
    float rsum = 0.f;             // regularizer accumulator (natural log)

    for (int b = gw; b < BB; b += TOTW){
        const float* tg = target + (size_t)b * CC + lane;
        float wt[4];
        #pragma unroll
        for (int k = 0; k < 4; k++) wt[k] = wv[k] * tg[32 * k];

        const float* lb = logits + (size_t)b * CC + lane;

        // ============ sigmoid expert pairs (sh, sh+3), base-2 ============
        #pragma unroll
        for (int sh = 0; sh < 3; sh++){
            const float* p0 = lb + (size_t)sh       * BB * CC;
            const float* p1 = lb + (size_t)(sh + 3) * BB * CC;
            float acl[4];
            #pragma unroll
            for (int k = 0; k < 4; k++){
                float shf = (sh == 0) ? 0.f : s_ss[sh][lane + 32 * k];
                float x  = fmaf(p0[32 * k], LOG2E, -shf);
                float tn = ex2f(-fabsf(x));                      // 2^{-|x|}
                float sp = lg2f(1.f + tn) + fmaxf(x, 0.f);       // softplus, log2
                float la = CLMP2(x - sp);                        // log2 clip(sig)
                float l1 = CLMP2(-sp);                           // log2 clip(1-sig)
                bs0 += wv[k] * l1 + wt[k] * (la - l1);

                float y   = fmaf(p1[32 * k], LOG2E, -shf);
                float tn2 = ex2f(-fabsf(y));
                float sp2 = lg2f(1.f + tn2) + fmaxf(y, 0.f);
                float la2u = y - sp2;                            // log2 sigmoid
                float la2 = CLMP2(la2u);
                float l12 = CLMP2(-sp2);
                bs1 += wv[k] * l12 + wt[k] * (la2 - l12);
                acl[k] = CLIP01(ex2f(la2u));                     // sigmoid(y)
            }
            #pragma unroll
            for (int k = 0; k < 4; k++){
                float ap = __shfl_sync(FULLM, acl[0], pi[k]);    // parent acl
                float d  = acl[k] - ap;
                float s2 = d * d;
                rsum += cf[k] * SPOLY(d, s2);
            }
        }

        // ============ local-softmax expert pairs (6+sh, 9+sh), base-2 ============
        #pragma unroll
        for (int sh = 0; sh < 3; sh++){
            const float* p0 = lb + (size_t)(6 + sh) * BB * CC;
            const float* p1 = lb + (size_t)(9 + sh) * BB * CC;
            float xa[4], xb[4], e0[4], e1[4];
            float ss0 = 0.f, ss1 = 0.f;
            #pragma unroll
            for (int k = 0; k < 4; k++){
                float shf = (sh == 0) ? 0.f : s_sm[sh][lane + 32 * k];
                xa[k] = fmaf(p0[32 * k], LOG2E, shf);  e0[k] = ex2f(xa[k]);  ss0 += e0[k];
                xb[k] = fmaf(p1[32 * k], LOG2E, shf);  e1[k] = ex2f(xb[k]);  ss1 += e1[k];
            }
            #pragma unroll
            for (int o = 16; o; o >>= 1){
                ss0 += __shfl_xor_sync(FULLM, ss0, o);
                ss1 += __shfl_xor_sync(FULLM, ss1, o);
            }
            // per-lane denominator candidates: lanes 0..15 -> S+eps-e_parent,
            // lanes 16..31 -> S+eps (no-correction case; sentinel pi=16)
            float pe0 = (lane < 16) ? e0[0] : 0.f;
            float pe1 = (lane < 16) ? e1[0] : 0.f;
            float vD0 = ss0 + EPSF - pe0;
            float vD1 = ss1 + EPSF - pe1;
            float lD0o = lg2f(vD0);
            float lD1o = lg2f(vD1);
            float rD1o = __fdividef(1.f, vD1);

            float ac[4];
            #pragma unroll
            for (int k = 0; k < 4; k++){
                int p = pi[k];
                float D0  = __shfl_sync(FULLM, vD0,  p);
                float lD0 = __shfl_sync(FULLM, lD0o, p);
                float D1  = __shfl_sync(FULLM, vD1,  p);
                float lD1 = __shfl_sync(FULLM, lD1o, p);
                float rD1 = __shfl_sync(FULLM, rD1o, p);
                float ldm0 = lg2f(D0 - e0[k]);
                float ldm1 = lg2f(D1 - e1[k]);
                float la0 = CLMP2(xa[k] - lD0), l10 = CLMP2(ldm0 - lD0);
                bs0 += wv[k] * l10 + wt[k] * (la0 - l10);
                float la1 = CLMP2(xb[k] - lD1), l11 = CLMP2(ldm1 - lD1);
                bs1 += wv[k] * l11 + wt[k] * (la1 - l11);
                ac[k] = CLIP01(e1[k] * rD1);                 // activation (reg)
            }
            #pragma unroll
            for (int k = 0; k < 4; k++){
                float ap = __shfl_sync(FULLM, ac[0], pi[k]); // parent activation
                float d  = ac[k] - ap;
                float s2 = d * d;
                rsum += cf[k] * SPOLY(d, s2);
            }
        }
    }

    // ---- deterministic block reduce (convert BCE back to natural log) ----
    float bsum = (bs0 + bs1) * LN2;
    #pragma unroll
    for (int o = 16; o; o >>= 1){
        bsum += __shfl_xor_sync(FULLM, bsum, o);
        rsum += __shfl_xor_sync(FULLM, rsum, o);
    }
    if (lane == 0){ s_redb[warp] = bsum; s_redr[warp] = rsum; }
    __syncthreads();
    if (threadIdx.x == 0){
        float pb = 0.f, pr = 0.f;
        #pragma unroll
        for (int w = 0; w < WPB; w++){ pb += s_redb[w]; pr += s_redr[w]; }
        g_pb[blockIdx.x] = pb;
        g_pr[blockIdx.x] = pr;
        __threadfence();
        unsigned old = atomicAdd(&g_done, 1u);
        s_last = (old == NBLK - 1);
    }
    __syncthreads();

    // ---- fused finish: last block does deterministic fp64 reduction ----
    if (s_last){
        __shared__ double sb[NTHR], sr[NTHR];
        int t = threadIdx.x;
        double db = 0.0, dr = 0.0;
        for (int i = t; i < NBLK; i += NTHR){
            db += (double)g_pb[i];
            dr += (double)g_pr[i];
        }
        sb[t] = db; sr[t] = dr;
        __syncthreads();
        for (int s = NTHR / 2; s; s >>= 1){
            if (t < s){ sb[t] += sb[t + s]; sr[t] += sr[t + s]; }
            __syncthreads();
        }
        if (t == 0){
            double loss = -sb[0] / ((double)BB * (double)CC);
            double nnz  = (double)g_nnz;
            double reg  = (nnz > 0.0) ? 4.0 * sr[0] / ((double)BB * nnz) : 0.0;
            out[0] = (float)(loss + reg);
            g_done = 0;   // reset ticket for next graph replay
        }
    }
}

extern "C" void kernel_launch(void* const* d_in, const int* in_sizes, int n_in,
                              void* d_out, int out_size)
{
    (void)in_sizes; (void)n_in; (void)out_size;
    const float* logits   = (const float*)d_in[0];
    const float* target   = (const float*)d_in[1];
    const float* weight   = (const float*)d_in[2];
    const float* prior_me = (const float*)d_in[3];
    const float* prior_ms = (const float*)d_in[4];
    const float* v1s      = (const float*)d_in[5];
    const float* v2s      = (const float*)d_in[6];
    const float* v1m      = (const float*)d_in[7];
    const float* v2m      = (const float*)d_in[8];

    prep_kernel<<<CC, CC>>>(prior_me, prior_ms);
    main_kernel<<<NBLK, NTHR>>>(logits, target, weight, v1s, v2s, v1m, v2m,
                                (float*)d_out);
}

// round 17
// speedup vs baseline: 1.0049x; 1.0049x over previous
#include <cuda_runtime.h>
#include <math.h>

#define CC 128
#define BB 16384
#define NBLK 1024             // 4096 warps -> exactly 4 rows/warp, one wave
#define NTHR 128
#define WPB 4                 // warps per block
#define TOTW (NBLK*WPB)       // 4096 warps

#define EPSF 1e-5f
#define LN2   0.6931471805599453f
#define LOG2E 1.4426950408889634f
// base-2 clamp bounds: log2(1e-5), log2(1-1e-5)
#define LOG2_EPS   -16.609640474436812f
#define LOG2_1MEPS -1.4427023e-05f

#define CLMP2(v) fminf(fmaxf((v), LOG2_EPS), LOG2_1MEPS)
#define CLIP01(a) fminf(fmaxf((a), EPSF), 1.f - EPSF)
// softplus(d), |d|<1, deg-6 Taylor (max abs err ~2.6e-5) -- natural log domain
#define SPOLY(d, s2) (LN2 + 0.5f*(d) + (s2)*(0.125f + (s2)*(-5.2083333e-3f + (s2)*3.4722222e-4f)))

#define FULLM 0xffffffffu

__device__ __forceinline__ float ex2f(float x){ float y; asm("ex2.approx.ftz.f32 %0,%1;" : "=f"(y) : "f"(x)); return y; }
__device__ __forceinline__ float lg2f(float x){ float y; asm("lg2.approx.ftz.f32 %0,%1;" : "=f"(y) : "f"(x)); return y; }

// ---- scratch (no allocations allowed) ----
__device__ float g_pb[NBLK];
__device__ float g_pr[NBLK];
__device__ int   g_pi[CC];     // parent column (0..15) per column, or 16 if none
__device__ float g_cf[CC];     // regularizer coef per column (0 if none)
__device__ float g_nnz;
__device__ unsigned int g_done = 0;  // last-block ticket (self-resetting)

// ---------------------------------------------------------------------------
// Prep: one block per column; ballot-based extraction.
// ---------------------------------------------------------------------------
__global__ void __launch_bounds__(CC)
prep_kernel(const float* __restrict__ prior_me,
            const float* __restrict__ prior_ms)
{
    __shared__ float    s_rs[CC];
    __shared__ unsigned s_bme[4], s_brs[4];
    const int c    = blockIdx.x;
    const int r    = threadIdx.x;
    const int warp = r >> 5;
    const int lane = r & 31;

    const float4* rp = (const float4*)(prior_ms + r * CC);
    float s = 0.f;
    #pragma unroll
    for (int j = 0; j < CC / 4; j++){
        float4 v = rp[j];
        s += v.x + v.y + v.z + v.w;
    }
    s_rs[r] = s;
    float mev = prior_me[r * CC + c];

    bool pme = (mev == 0.f) && (r != c);
    bool prs = (s > 0.f);
    unsigned bme = __ballot_sync(FULLM, pme);
    unsigned brs = __ballot_sync(FULLM, prs);
    if (lane == 0){ s_bme[warp] = bme; s_brs[warp] = brs; }
    __syncthreads();

    if (r == 0){
        int pid = -1;
        #pragma unroll
        for (int w = 0; w < 4; w++){
            unsigned m = s_bme[w];
            if (m && pid < 0) pid = w * 32 + (__ffs(m) - 1);
        }
        float cf = 0.f;
        if (pid >= 0){
            float v = prior_ms[pid * CC + c];
            if (v != 0.f && s_rs[pid] > 0.f) cf = v / s_rs[pid];
        }
        g_pi[c] = (pid >= 0) ? pid : 16;   // 16 = "no parent" sentinel entry
        g_cf[c] = cf;
    }
    if (r == 32 && c == 0){
        g_nnz = (float)(__popc(s_brs[0]) + __popc(s_brs[1]) +
                        __popc(s_brs[2]) + __popc(s_brs[3]));
    }
}

// ---------------------------------------------------------------------------
// Main fused kernel, base-2 log domain, strided lane layout (c = lane + 32k).
// Parents (cols 0..15) live at k=0 of lanes 0..15. Per-warp smem parent
// tables (17 entries incl. sentinel) carry the shared denominators:
// build is 17-lane SIMD (4 MUFU warp-instrs), consume is 2 LDS per k.
// No SHFL.IDX; only reduction shuffles. One __syncwarp per expert pair.
// ---------------------------------------------------------------------------
__global__ void __launch_bounds__(NTHR, 8)
main_kernel(const float* __restrict__ logits,
            const float* __restrict__ target,
            const float* __restrict__ weight,
            const float* __restrict__ v1s, const float* __restrict__ v2s,
            const float* __restrict__ v1m, const float* __restrict__ v2m,
            float* __restrict__ out)
{
    __shared__ float  s_ss[3][CC];       // sigmoid shifts, prescaled by LOG2E
    __shared__ float  s_sm[3][CC];       // softmax shifts, prescaled by LOG2E
    __shared__ float  s_pa[2][WPB][20];  // sigmoid parent-acl tables (ping-pong)
    __shared__ float4 s_t4[2][WPB][20];  // softmax tables {vD0,lD0,vD1,lD1}
    __shared__ float2 s_t2[2][WPB][20];  // softmax tables {rD1, ap_clipped}
    __shared__ float  s_redb[WPB], s_redr[WPB];
    __shared__ bool   s_last;

    for (int c = threadIdx.x; c < CC; c += NTHR){
        float a1 = v1s[c], a2 = v2s[c];
        s_ss[0][c] = 0.f;
        s_ss[1][c] = a1 * LOG2E;
        s_ss[2][c] = (a1 - a2) * LOG2E;
        float m1 = v1m[c], m2 = v2m[c];
        s_sm[0][c] = 0.f;
        s_sm[1][c] = m1 * LOG2E;
        s_sm[2][c] = (m1 - m2) * LOG2E;
    }
    __syncthreads();

    const int warp = threadIdx.x >> 5;
    const int lane = threadIdx.x & 31;
    const int gw   = blockIdx.x * WPB + warp;

    int   pi[4];
    float cf[4], wv[4];
    #pragma unroll
    for (int k = 0; k < 4; k++){
        int c = lane + 32 * k;
        pi[k] = g_pi[c];
        cf[k] = g_cf[c];
        wv[k] = weight[c];
    }

    float bs0 = 0.f, bs1 = 0.f;   // BCE accumulators (base-2 log units)
    float rsum = 0.f;             // regularizer accumulator (natural log)

    for (int b = gw; b < BB; b += TOTW){
        const float* tg = target + (size_t)b * CC + lane;
        float wt[4];
        #pragma unroll
        for (int k = 0; k < 4; k++) wt[k] = wv[k] * tg[32 * k];

        const float* lb = logits + (size_t)b * CC + lane;

        // ============ sigmoid expert pairs (sh, sh+3), base-2 ============
        #pragma unroll
        for (int sh = 0; sh < 3; sh++){
            const float* p0 = lb + (size_t)sh       * BB * CC;
            const float* p1 = lb + (size_t)(sh + 3) * BB * CC;
            float* ta = s_pa[sh & 1][warp];
            float acl[4];
            #pragma unroll
            for (int k = 0; k < 4; k++){
                float shf = (sh == 0) ? 0.f : s_ss[sh][lane + 32 * k];
                float x  = fmaf(p0[32 * k], LOG2E, -shf);
                float tn = ex2f(-fabsf(x));                      // 2^{-|x|}
                float sp = lg2f(1.f + tn) + fmaxf(x, 0.f);       // softplus, log2
                float la = CLMP2(x - sp);                        // log2 clip(sig)
                float l1 = CLMP2(-sp);                           // log2 clip(1-sig)
                bs0 += wv[k] * l1 + wt[k] * (la - l1);

                float y   = fmaf(p1[32 * k], LOG2E, -shf);
                float tn2 = ex2f(-fabsf(y));
                float sp2 = lg2f(1.f + tn2) + fmaxf(y, 0.f);
                float la2u = y - sp2;                            // log2 sigmoid
                float la2 = CLMP2(la2u);
                float l12 = CLMP2(-sp2);
                bs1 += wv[k] * l12 + wt[k] * (la2 - l12);
                acl[k] = CLIP01(ex2f(la2u));                     // sigmoid(y)
            }
            if (lane <= 16) ta[lane] = (lane < 16) ? acl[0] : 0.f;
            __syncwarp();
            #pragma unroll
            for (int k = 0; k < 4; k++){
                float ap = ta[pi[k]];                 // parent acl (sentinel 0)
                float d  = acl[k] - ap;
                float s2 = d * d;
                rsum += cf[k] * SPOLY(d, s2);
            }
        }

        // ============ local-softmax expert pairs (6+sh, 9+sh), base-2 ============
        #pragma unroll
        for (int sh = 0; sh < 3; sh++){
            const float* p0 = lb + (size_t)(6 + sh) * BB * CC;
            const float* p1 = lb + (size_t)(9 + sh) * BB * CC;
            float4* t4 = s_t4[sh & 1][warp];
            float2* t2 = s_t2[sh & 1][warp];
            float xa[4], xb[4], e0[4], e1[4];
            float ss0 = 0.f, ss1 = 0.f;
            #pragma unroll
            for (int k = 0; k < 4; k++){
                float shf = (sh == 0) ? 0.f : s_sm[sh][lane + 32 * k];
                xa[k] = fmaf(p0[32 * k], LOG2E, shf);  e0[k] = ex2f(xa[k]);  ss0 += e0[k];
                xb[k] = fmaf(p1[32 * k], LOG2E, shf);  e1[k] = ex2f(xb[k]);  ss1 += e1[k];
            }
            #pragma unroll
            for (int o = 16; o; o >>= 1){
                ss0 += __shfl_xor_sync(FULLM, ss0, o);
                ss1 += __shfl_xor_sync(FULLM, ss1, o);
            }
            // 17-lane SIMD table build: entry p = child-denominators for parent p,
            // entry 16 = sentinel (no correction). ap = parent activation, clipped.
            if (lane <= 16){
                float pe0 = (lane < 16) ? e0[0] : 0.f;
                float pe1 = (lane < 16) ? e1[0] : 0.f;
                float vD0 = ss0 + EPSF - pe0;
                float vD1 = ss1 + EPSF - pe1;
                float lD0 = lg2f(vD0);
                float lD1 = lg2f(vD1);
                float rD1 = __fdividef(1.f, vD1);
                float rS1 = __fdividef(1.f, ss1 + EPSF);
                float ap  = CLIP01(pe1 * rS1);
                t4[lane] = make_float4(vD0, lD0, vD1, lD1);
                t2[lane] = make_float2(rD1, ap);
            }
            __syncwarp();
            #pragma unroll
            for (int k = 0; k < 4; k++){
                float4 q = t4[pi[k]];
                float2 r = t2[pi[k]];
                float ldm0 = lg2f(q.x - e0[k]);
                float ldm1 = lg2f(q.z - e1[k]);
                float la0 = CLMP2(xa[k] - q.y), l10 = CLMP2(ldm0 - q.y);
                bs0 += wv[k] * l10 + wt[k] * (la0 - l10);
                float la1 = CLMP2(xb[k] - q.w), l11 = CLMP2(ldm1 - q.w);
                bs1 += wv[k] * l11 + wt[k] * (la1 - l11);
                float ac = CLIP01(e1[k] * r.x);       // child activation
                float d  = ac - r.y;                  // - parent activation
                float s2 = d * d;
                rsum += cf[k] * SPOLY(d, s2);
            }
        }
    }

    // ---- deterministic block reduce (convert BCE back to natural log) ----
    float bsum = (bs0 + bs1) * LN2;
    #pragma unroll
    for (int o = 16; o; o >>= 1){
        bsum += __shfl_xor_sync(FULLM, bsum, o);
        rsum += __shfl_xor_sync(FULLM, rsum, o);
    }
    if (lane == 0){ s_redb[warp] = bsum; s_redr[warp] = rsum; }
    __syncthreads();
    if (threadIdx.x == 0){
        float pb = 0.f, pr = 0.f;
        #pragma unroll
        for (int w = 0; w < WPB; w++){ pb += s_redb[w]; pr += s_redr[w]; }
        g_pb[blockIdx.x] = pb;
        g_pr[blockIdx.x] = pr;
        __threadfence();
        unsigned old = atomicAdd(&g_done, 1u);
        s_last = (old == NBLK - 1);
    }
    __syncthreads();

    // ---- fused finish: last block does deterministic fp64 reduction ----
    if (s_last){
        __shared__ double sb[NTHR], sr[NTHR];
        int t = threadIdx.x;
        double db = 0.0, dr = 0.0;
        for (int i = t; i < NBLK; i += NTHR){
            db += (double)g_pb[i];
            dr += (double)g_pr[i];
        }
        sb[t] = db; sr[t] = dr;
        __syncthreads();
        for (int s = NTHR / 2; s; s >>= 1){
            if (t < s){ sb[t] += sb[t + s]; sr[t] += sr[t + s]; }
            __syncthreads();
        }
        if (t == 0){
            double loss = -sb[0] / ((double)BB * (double)CC);
            double nnz  = (double)g_nnz;
            double reg  = (nnz > 0.0) ? 4.0 * sr[0] / ((double)BB * nnz) : 0.0;
            out[0] = (float)(loss + reg);
            g_done = 0;   // reset ticket for next graph replay
        }
    }
}

extern "C" void kernel_launch(void* const* d_in, const int* in_sizes, int n_in,
                              void* d_out, int out_size)
{
    (void)in_sizes; (void)n_in; (void)out_size;
    const float* logits   = (const float*)d_in[0];
    const float* target   = (const float*)d_in[1];
    const float* weight   = (const float*)d_in[2];
    const float* prior_me = (const float*)d_in[3];
    const float* prior_ms = (const float*)d_in[4];
    const float* v1s      = (const float*)d_in[5];
    const float* v2s      = (const float*)d_in[6];
    const float* v1m      = (const float*)d_in[7];
    const float* v2m      = (const float*)d_in[8];

    prep_kernel<<<CC, CC>>>(prior_me, prior_ms);
    main_kernel<<<NBLK, NTHR>>>(logits, target, weight, v1s, v2s, v1m, v2m,
                                (float*)d_out);
}